// round 13
// baseline (speedup 1.0000x reference)
#include <cuda_runtime.h>
#include <cstdint>

#define IN_DIM   256
#define OUT_DIM  256
#define N_KNOTS  9
#define NB       5
#define B_TILE   16
#define IHALF    128             // i-range per CTA
#define THREADS  160             // 4 consumer warps + 1 producer warp
#define CW       (OUT_DIM * NB)  // 1280 coeff words per i-row
#define NROWS_B  4096

#define STAGES        3
#define STAGE_WORDS   (2 * CW)              // 2560 (2 i-rows per stage)
#define NPAIR         (IHALF / 2)           // 64

#define MBAR_WORDS 16
#define RING_OFF   MBAR_WORDS
#define RING_WORDS (STAGES * STAGE_WORDS)    // 7680
#define BASIS_OFF  (RING_OFF + RING_WORDS)
#define SB_WORDS   (IHALF * NB * B_TILE)     // 10240 (40 KB)
#define SMEM_WORDS (BASIS_OFF + SB_WORDS)
#define SMEM_BYTES (SMEM_WORDS * 4)          // 71,744 B -> 3 CTAs/SM

// partial-y scratch: [ihalf][B][OUT_DIM]  (8 MB)
__device__ float g_ypart[2 * NROWS_B * OUT_DIM];

// ---- mbarrier PTX helpers -------------------------------------------------
#define MBAR_INIT(addr, cnt) \
    asm volatile("mbarrier.init.shared.b64 [%0], %1;" :: "r"(addr), "r"(cnt) : "memory")
#define MBAR_ARRIVE(addr) \
    asm volatile("mbarrier.arrive.shared.b64 _, [%0];" :: "r"(addr) : "memory")
#define MBAR_WAIT(addr, parity) do {                                           \
    asm volatile(                                                              \
        "{\n\t.reg .pred P;\n\t"                                              \
        "WL_%=:\n\t"                                                          \
        "mbarrier.try_wait.parity.acquire.cta.shared::cta.b64 P, [%0], %1, 0x989680;\n\t" \
        "@P bra.uni WD_%=;\n\t"                                               \
        "bra.uni WL_%=;\n\t"                                                  \
        "WD_%=:\n\t}"                                                         \
        :: "r"(addr), "r"(parity) : "memory");                                \
} while (0)

__device__ __forceinline__ uint32_t smem_u32(const void* p) {
    uint32_t a;
    asm("{ .reg .u64 t; cvta.to.shared.u64 t, %1; cvt.u32.u64 %0, t; }"
        : "=r"(a) : "l"(p));
    return a;
}

__global__ __launch_bounds__(THREADS, 3)
void kan_kernel(const float* __restrict__ x,
                const float* __restrict__ grids,
                const float* __restrict__ coef,
                float* __restrict__ acts)
{
    extern __shared__ float smem[];
    float* ring   = smem + RING_OFF;    // [stage3][row2][1280] native [o][n]
    float* sbasis = smem + BASIS_OFF;   // [iloc][n][r16]
    const uint32_t mb = smem_u32(smem); // full[s]=mb+s*16, empty[s]=mb+s*16+8

    const int t     = threadIdx.x;
    const int wid   = t >> 5;
    const int c     = blockIdx.x;
    const int ihalf = c & 1;
    const int ilo   = ihalf * IHALF;
    const int b0    = (c >> 1) * B_TILE;

    if (t == 0) {
        #pragma unroll
        for (int s = 0; s < STAGES; s++) {
            MBAR_INIT(mb + s * 16,     32);  // full: 32 producer lanes
            MBAR_INIT(mb + s * 16 + 8,  4);  // empty: 4 elected consumer lanes
        }
    }

    // ------- Phase 1: basis. 128 consumer threads x 1 i-value x 16 rows -------
    if (t < 128) {
        const int i = ilo + t;               // global input dim
        float tk[N_KNOTS];
        #pragma unroll
        for (int k = 0; k < N_KNOTS; k++) tk[k] = grids[i * N_KNOTS + k];

        float iL1[7], iR1[7], iL2[6], iR2[6], iL3[5], iR3[5];
        #pragma unroll
        for (int j = 0; j < 7; j++) { iL1[j] = 1.f / (tk[j+1] - tk[j]); iR1[j] = 1.f / (tk[j+2] - tk[j+1]); }
        #pragma unroll
        for (int j = 0; j < 6; j++) { iL2[j] = 1.f / (tk[j+2] - tk[j]); iR2[j] = 1.f / (tk[j+3] - tk[j+1]); }
        #pragma unroll
        for (int j = 0; j < 5; j++) { iL3[j] = 1.f / (tk[j+3] - tk[j]); iR3[j] = 1.f / (tk[j+4] - tk[j+1]); }

        const int rot = t & 15;
        #pragma unroll
        for (int rr = 0; rr < B_TILE; rr++) {
            const int r = (rr + rot) & 15;   // bank-spreading rotation
            const float xv = x[(size_t)(b0 + r) * IN_DIM + i];
            float bas[8];
            #pragma unroll
            for (int j = 0; j < 8; j++)
                bas[j] = (xv >= tk[j] && xv < tk[j+1]) ? 1.0f : 0.0f;
            #pragma unroll
            for (int j = 0; j < 7; j++)
                bas[j] = (xv - tk[j]) * iL1[j] * bas[j] + (tk[j+2] - xv) * iR1[j] * bas[j+1];
            #pragma unroll
            for (int j = 0; j < 6; j++)
                bas[j] = (xv - tk[j]) * iL2[j] * bas[j] + (tk[j+3] - xv) * iR2[j] * bas[j+1];
            #pragma unroll
            for (int j = 0; j < 5; j++)
                bas[j] = (xv - tk[j]) * iL3[j] * bas[j] + (tk[j+4] - xv) * iR3[j] * bas[j+1];

            #pragma unroll
            for (int n = 0; n < NB; n++)
                sbasis[(t * NB + n) * B_TILE + r] = bas[n];
        }
    }
    __syncthreads();   // publishes basis + mbarrier init; the ONLY block barrier

    if (wid == 4) {
        // ---------------- Producer warp: stream this CTA's 128 coeff rows -----
        const int lane = t & 31;
        int s = 0, ph = 1;                      // fresh empties pass parity 1
        for (int p = 0; p < NPAIR; p++) {
            MBAR_WAIT(mb + s * 16 + 8, ph);     // wait stage empty
            const float4* src = reinterpret_cast<const float4*>(
                coef + (size_t)(ilo + 2 * p) * CW);
            float4* dst = reinterpret_cast<float4*>(ring + s * STAGE_WORDS);
            float4 v[20];
            #pragma unroll
            for (int k = 0; k < 20; k++) v[k] = src[lane + 32 * k];
            #pragma unroll
            for (int k = 0; k < 20; k++) dst[lane + 32 * k] = v[k];
            MBAR_ARRIVE(mb + s * 16);           // all 32 lanes -> full
            if (++s == STAGES) { s = 0; ph ^= 1; }
        }
    } else {
        // -------- Consumer warps: thread = 4 cols x 8 rows (two aligned halves)
        const int o4 = (t & 63) * 4;
        const int r0 = (t >> 6) * 8;            // row group start: 0 or 8

        float4 acc[8];
        #pragma unroll
        for (int r = 0; r < 8; r++) acc[r] = make_float4(0.f, 0.f, 0.f, 0.f);

        float* actp = acts + (size_t)(b0 + r0) * (IN_DIM * OUT_DIM) + o4;

        int s = 0, ph = 0;
        for (int p = 0; p < NPAIR; p++) {
            MBAR_WAIT(mb + s * 16, ph);         // wait stage full (acquire)

            #pragma unroll
            for (int sub = 0; sub < 2; sub++) {
                const int iloc = 2 * p + sub;
                const int i    = ilo + iloc;

                // coeff: 20 consecutive words at o4*5 -> 5 conflict-free LDS.128
                float4 q[5];
                const float4* cb = reinterpret_cast<const float4*>(
                    &ring[s * STAGE_WORDS + sub * CW + o4 * NB]);
                #pragma unroll
                for (int j = 0; j < 5; j++) q[j] = cb[j];
                const float* f = reinterpret_cast<const float*>(q); // f[o*5+n]

                #pragma unroll
                for (int half = 0; half < 2; half++) {
                    // basis: 4 rows per n at aligned offset, broadcast LDS.128
                    float4 bs[NB];
                    #pragma unroll
                    for (int n = 0; n < NB; n++)
                        bs[n] = *reinterpret_cast<const float4*>(
                            &sbasis[(iloc * NB + n) * B_TILE + r0 + half * 4]);

                    #pragma unroll
                    for (int r = 0; r < 4; r++) {
                        const float bb0 = reinterpret_cast<const float*>(&bs[0])[r];
                        const float bb1 = reinterpret_cast<const float*>(&bs[1])[r];
                        const float bb2 = reinterpret_cast<const float*>(&bs[2])[r];
                        const float bb3 = reinterpret_cast<const float*>(&bs[3])[r];
                        const float bb4 = reinterpret_cast<const float*>(&bs[4])[r];
                        float4 v;
                        v.x = bb0*f[ 0] + bb1*f[ 1] + bb2*f[ 2] + bb3*f[ 3] + bb4*f[ 4];
                        v.y = bb0*f[ 5] + bb1*f[ 6] + bb2*f[ 7] + bb3*f[ 8] + bb4*f[ 9];
                        v.z = bb0*f[10] + bb1*f[11] + bb2*f[12] + bb3*f[13] + bb4*f[14];
                        v.w = bb0*f[15] + bb1*f[16] + bb2*f[17] + bb3*f[18] + bb4*f[19];

                        const int rr = half * 4 + r;
                        __stcs(reinterpret_cast<float4*>(
                            actp + (size_t)rr * (IN_DIM * OUT_DIM) + i * OUT_DIM), v);

                        acc[rr].x += v.x; acc[rr].y += v.y;
                        acc[rr].z += v.z; acc[rr].w += v.w;
                    }
                }
            }

            __syncwarp();
            if ((t & 31) == 0) MBAR_ARRIVE(mb + s * 16 + 8);   // release stage
            if (++s == STAGES) { s = 0; ph ^= 1; }
        }

        // partial y for this i-half
        float* yp = g_ypart + (size_t)ihalf * (NROWS_B * OUT_DIM)
                  + (size_t)(b0 + r0) * OUT_DIM + o4;
        #pragma unroll
        for (int r = 0; r < 8; r++)
            *reinterpret_cast<float4*>(yp + (size_t)r * OUT_DIM) = acc[r];
    }
}

// ---- final reduce: y = ypart0 + ypart1 (1M floats) --------------------------
__global__ __launch_bounds__(256)
void kan_yreduce(float* __restrict__ y)
{
    const int idx = blockIdx.x * 256 + threadIdx.x;   // float4 index
    const float4* p0 = reinterpret_cast<const float4*>(g_ypart);
    const float4* p1 = reinterpret_cast<const float4*>(g_ypart + NROWS_B * OUT_DIM);
    float4 a = p0[idx], b = p1[idx];
    a.x += b.x; a.y += b.y; a.z += b.z; a.w += b.w;
    reinterpret_cast<float4*>(y)[idx] = a;
}

extern "C" void kernel_launch(void* const* d_in, const int* in_sizes, int n_in,
                              void* d_out, int out_size)
{
    const float* x     = (const float*)d_in[0];
    const float* grids = (const float*)d_in[1];
    const float* coef  = (const float*)d_in[2];

    const int B = in_sizes[0] / IN_DIM;   // 4096

    float* y    = (float*)d_out;
    float* acts = (float*)d_out + (size_t)B * OUT_DIM;

    cudaFuncSetAttribute(kan_kernel,
                         cudaFuncAttributeMaxDynamicSharedMemorySize, SMEM_BYTES);
    kan_kernel<<<(B / B_TILE) * 2, THREADS, SMEM_BYTES>>>(x, grids, coef, acts);

    const int nf4 = B * OUT_DIM / 4;      // 262144
    kan_yreduce<<<nf4 / 256, 256>>>(y);
}

// round 14
// speedup vs baseline: 1.1280x; 1.1280x over previous
#include <cuda_runtime.h>
#include <cstdint>

#define IN_DIM   256
#define OUT_DIM  256
#define N_KNOTS  9
#define NB       5
#define B_TILE   16
#define THREADS  160             // 4 consumer warps + 1 producer warp
#define CW       (OUT_DIM * NB)  // 1280 coeff words per i-row

#define STAGES        3
#define STAGE_WORDS   (2 * CW)                // 2560 (2 i-rows per stage)
#define NPAIR         (IN_DIM / 2)            // 128

#define MBAR_WORDS 16
#define RING_OFF   MBAR_WORDS
#define RING_WORDS (STAGES * STAGE_WORDS)      // 7680
#define BASIS_OFF  (RING_OFF + RING_WORDS)
#define SB_WORDS   (IN_DIM * NB * B_TILE)      // 20480
#define SMEM_WORDS (BASIS_OFF + SB_WORDS)
#define SMEM_BYTES (SMEM_WORDS * 4)            // 112,704 B -> 2 CTAs/SM

// ---- mbarrier PTX helpers -------------------------------------------------
#define MBAR_INIT(addr, cnt) \
    asm volatile("mbarrier.init.shared.b64 [%0], %1;" :: "r"(addr), "r"(cnt) : "memory")
#define MBAR_ARRIVE(addr) \
    asm volatile("mbarrier.arrive.shared.b64 _, [%0];" :: "r"(addr) : "memory")
#define MBAR_WAIT(addr, parity) do {                                           \
    asm volatile(                                                              \
        "{\n\t.reg .pred P;\n\t"                                              \
        "WL_%=:\n\t"                                                          \
        "mbarrier.try_wait.parity.acquire.cta.shared::cta.b64 P, [%0], %1, 0x989680;\n\t" \
        "@P bra.uni WD_%=;\n\t"                                               \
        "bra.uni WL_%=;\n\t"                                                  \
        "WD_%=:\n\t}"                                                         \
        :: "r"(addr), "r"(parity) : "memory");                                \
} while (0)

// ---- packed f32x2 helpers (Blackwell) ---------------------------------------
#define PACK2(d, x, y) \
    asm("mov.b64 %0, {%1,%2};" : "=l"(d) \
        : "r"(__float_as_uint(x)), "r"(__float_as_uint(y)))
#define UNPK2(x, y, s) do { unsigned int _lo, _hi;                       \
    asm("mov.b64 {%0,%1}, %2;" : "=r"(_lo), "=r"(_hi) : "l"(s));         \
    (x) = __uint_as_float(_lo); (y) = __uint_as_float(_hi); } while (0)
#define FMA2(d, a, b, c) \
    asm("fma.rn.f32x2 %0, %1, %2, %3;" : "=l"(d) : "l"(a), "l"(b), "l"(c))
#define MUL2(d, a, b) \
    asm("mul.rn.f32x2 %0, %1, %2;" : "=l"(d) : "l"(a), "l"(b))
#define ADD2(d, a, b) \
    asm("add.rn.f32x2 %0, %1, %2;" : "=l"(d) : "l"(a), "l"(b))

__device__ __forceinline__ uint32_t smem_u32(const void* p) {
    uint32_t a;
    asm("{ .reg .u64 t; cvta.to.shared.u64 t, %1; cvt.u32.u64 %0, t; }"
        : "=r"(a) : "l"(p));
    return a;
}

__global__ __launch_bounds__(THREADS, 2)
void kan_kernel(const float* __restrict__ x,
                const float* __restrict__ grids,
                const float* __restrict__ coef,
                float* __restrict__ y,
                float* __restrict__ acts)
{
    extern __shared__ float smem[];
    float* ring   = smem + RING_OFF;    // [stage3][row2][1280] native [o][n]
    float* sbasis = smem + BASIS_OFF;   // [i][n][r16]
    const uint32_t mb = smem_u32(smem); // full[s]=mb+s*16, empty[s]=mb+s*16+8

    const int t   = threadIdx.x;
    const int wid = t >> 5;
    const int b0  = blockIdx.x * B_TILE;

    if (t == 0) {
        #pragma unroll
        for (int s = 0; s < STAGES; s++) {
            MBAR_INIT(mb + s * 16,     32);  // full: 32 producer lanes
            MBAR_INIT(mb + s * 16 + 8,  4);  // empty: 4 elected consumer lanes
        }
    }

    // ------- Phase 1: basis. 128 consumer threads x 2 i-values x 16 rows ------
    if (t < 128) {
        #pragma unroll
        for (int half = 0; half < 2; half++) {
            const int i = t + 128 * half;
            float tk[N_KNOTS];
            #pragma unroll
            for (int k = 0; k < N_KNOTS; k++) tk[k] = grids[i * N_KNOTS + k];

            float iL1[7], iR1[7], iL2[6], iR2[6], iL3[5], iR3[5];
            #pragma unroll
            for (int j = 0; j < 7; j++) { iL1[j] = 1.f / (tk[j+1] - tk[j]); iR1[j] = 1.f / (tk[j+2] - tk[j+1]); }
            #pragma unroll
            for (int j = 0; j < 6; j++) { iL2[j] = 1.f / (tk[j+2] - tk[j]); iR2[j] = 1.f / (tk[j+3] - tk[j+1]); }
            #pragma unroll
            for (int j = 0; j < 5; j++) { iL3[j] = 1.f / (tk[j+3] - tk[j]); iR3[j] = 1.f / (tk[j+4] - tk[j+1]); }

            const int rot = i & 15;
            #pragma unroll
            for (int rr = 0; rr < B_TILE; rr++) {
                const int r = (rr + rot) & 15;
                const float xv = x[(size_t)(b0 + r) * IN_DIM + i];
                float bas[8];
                #pragma unroll
                for (int j = 0; j < 8; j++)
                    bas[j] = (xv >= tk[j] && xv < tk[j+1]) ? 1.0f : 0.0f;
                #pragma unroll
                for (int j = 0; j < 7; j++)
                    bas[j] = (xv - tk[j]) * iL1[j] * bas[j] + (tk[j+2] - xv) * iR1[j] * bas[j+1];
                #pragma unroll
                for (int j = 0; j < 6; j++)
                    bas[j] = (xv - tk[j]) * iL2[j] * bas[j] + (tk[j+3] - xv) * iR2[j] * bas[j+1];
                #pragma unroll
                for (int j = 0; j < 5; j++)
                    bas[j] = (xv - tk[j]) * iL3[j] * bas[j] + (tk[j+4] - xv) * iR3[j] * bas[j+1];

                #pragma unroll
                for (int n = 0; n < NB; n++)
                    sbasis[(i * NB + n) * B_TILE + r] = bas[n];
            }
        }
    }
    __syncthreads();   // publishes basis + mbarrier init; the ONLY block barrier

    if (wid == 4) {
        // ---------------- Producer warp: stream coeff rows through the ring ---
        const int lane = t & 31;
        int s = 0, ph = 1;                      // fresh empties pass parity 1
        for (int p = 0; p < NPAIR; p++) {
            MBAR_WAIT(mb + s * 16 + 8, ph);     // wait stage empty
            const float4* src = reinterpret_cast<const float4*>(
                coef + (size_t)(2 * p) * CW);
            float4* dst = reinterpret_cast<float4*>(ring + s * STAGE_WORDS);
            float4 v[20];
            #pragma unroll
            for (int k = 0; k < 20; k++) v[k] = src[lane + 32 * k];
            #pragma unroll
            for (int k = 0; k < 20; k++) dst[lane + 32 * k] = v[k];
            MBAR_ARRIVE(mb + s * 16);           // all 32 lanes -> full
            if (++s == STAGES) { s = 0; ph ^= 1; }
        }
    } else {
        // ---- Consumer warps: thread = 4 cols x 8 rows, packed f32x2 math ------
        const int o4 = (t & 63) * 4;
        const int r0 = (t >> 6) * 8;            // row group start: 0 or 8

        // acc[g*4+og]: packed (row r0+2g, row r0+2g+1) for column o4+og
        unsigned long long acc[16];
        #pragma unroll
        for (int k = 0; k < 16; k++) acc[k] = 0ull;

        float* actp = acts + (size_t)(b0 + r0) * (IN_DIM * OUT_DIM) + o4;

        int s = 0, ph = 0;
        for (int p = 0; p < NPAIR; p++) {
            MBAR_WAIT(mb + s * 16, ph);         // wait stage full (acquire)

            #pragma unroll
            for (int sub = 0; sub < 2; sub++) {
                const int i = 2 * p + sub;

                // coeff: 20 consecutive words at o4*5 -> 5 conflict-free LDS.128
                float4 q[5];
                const float4* cb = reinterpret_cast<const float4*>(
                    &ring[s * STAGE_WORDS + sub * CW + o4 * NB]);
                #pragma unroll
                for (int j = 0; j < 5; j++) q[j] = cb[j];
                const float* f = reinterpret_cast<const float*>(q); // f[o*5+n]

                #pragma unroll
                for (int half = 0; half < 2; half++) {
                    // basis rows r0h..r0h+3: pairs come free from LDS.128
                    unsigned long long bp[NB][2];
                    #pragma unroll
                    for (int n = 0; n < NB; n++) {
                        const float4 b4 = *reinterpret_cast<const float4*>(
                            &sbasis[(i * NB + n) * B_TILE + r0 + half * 4]);
                        PACK2(bp[n][0], b4.x, b4.y);
                        PACK2(bp[n][1], b4.z, b4.w);
                    }

                    unsigned long long vb[2][4];
                    #pragma unroll
                    for (int og = 0; og < 4; og++) {
                        unsigned long long cs0, cs1, cs2, cs3, cs4;
                        PACK2(cs0, f[og*5+0], f[og*5+0]);
                        PACK2(cs1, f[og*5+1], f[og*5+1]);
                        PACK2(cs2, f[og*5+2], f[og*5+2]);
                        PACK2(cs3, f[og*5+3], f[og*5+3]);
                        PACK2(cs4, f[og*5+4], f[og*5+4]);
                        #pragma unroll
                        for (int rp = 0; rp < 2; rp++) {
                            unsigned long long v;
                            MUL2(v, bp[0][rp], cs0);
                            FMA2(v, bp[1][rp], cs1, v);
                            FMA2(v, bp[2][rp], cs2, v);
                            FMA2(v, bp[3][rp], cs3, v);
                            FMA2(v, bp[4][rp], cs4, v);
                            const int g = half * 2 + rp;
                            ADD2(acc[g*4+og], acc[g*4+og], v);
                            vb[rp][og] = v;
                        }
                    }

                    // stores: unpack row pairs into two float4 rows
                    #pragma unroll
                    for (int rp = 0; rp < 2; rp++) {
                        float4 vlo, vhi;
                        UNPK2(vlo.x, vhi.x, vb[rp][0]);
                        UNPK2(vlo.y, vhi.y, vb[rp][1]);
                        UNPK2(vlo.z, vhi.z, vb[rp][2]);
                        UNPK2(vlo.w, vhi.w, vb[rp][3]);
                        const int rr = half * 4 + rp * 2;
                        __stcs(reinterpret_cast<float4*>(
                            actp + (size_t)rr * (IN_DIM * OUT_DIM) + i * OUT_DIM), vlo);
                        __stcs(reinterpret_cast<float4*>(
                            actp + (size_t)(rr + 1) * (IN_DIM * OUT_DIM) + i * OUT_DIM), vhi);
                    }
                }
            }

            __syncwarp();
            if ((t & 31) == 0) MBAR_ARRIVE(mb + s * 16 + 8);   // release stage
            if (++s == STAGES) { s = 0; ph ^= 1; }
        }

        // ------- y epilogue: unpack packed accumulators -----------------------
        float* yp = y + (size_t)(b0 + r0) * OUT_DIM + o4;
        #pragma unroll
        for (int g = 0; g < 4; g++) {
            float4 vlo, vhi;
            UNPK2(vlo.x, vhi.x, acc[g*4+0]);
            UNPK2(vlo.y, vhi.y, acc[g*4+1]);
            UNPK2(vlo.z, vhi.z, acc[g*4+2]);
            UNPK2(vlo.w, vhi.w, acc[g*4+3]);
            *reinterpret_cast<float4*>(yp + (size_t)(2*g)     * OUT_DIM) = vlo;
            *reinterpret_cast<float4*>(yp + (size_t)(2*g + 1) * OUT_DIM) = vhi;
        }
    }
}

extern "C" void kernel_launch(void* const* d_in, const int* in_sizes, int n_in,
                              void* d_out, int out_size)
{
    const float* x     = (const float*)d_in[0];
    const float* grids = (const float*)d_in[1];
    const float* coef  = (const float*)d_in[2];

    const int B = in_sizes[0] / IN_DIM;   // 4096

    float* y    = (float*)d_out;
    float* acts = (float*)d_out + (size_t)B * OUT_DIM;

    cudaFuncSetAttribute(kan_kernel,
                         cudaFuncAttributeMaxDynamicSharedMemorySize, SMEM_BYTES);
    kan_kernel<<<B / B_TILE, THREADS, SMEM_BYTES>>>(x, grids, coef, y, acts);
}